// round 4
// baseline (speedup 1.0000x reference)
#include <cuda_runtime.h>
#include <math.h>

// Problem constants
#define BB 16
#define CC 32
#define HH 224
#define WW 224

// Scratch (static __device__ arrays: allowed; no runtime allocation)
__device__ float g_s1[9216];             // conv1 signs, layout [ci][tap][co]
__device__ float g_s2[9216];             // conv2 signs, layout [ci][tap][co]
__device__ float g_lut1[64];             // t0[32], diff[32]
__device__ float g_lut2[64];             // t0[32], diff[32]
__device__ unsigned char g_h1[BB*CC*HH*WW];  // intermediate levels 0..7

// ---------------------------------------------------------------------------
// Prep: binarize weights (sign(w - mean)) into [ci][tap][co] layout, and fold
// BN into LUT threshold (t0, diff) per channel:
//   std = sqrt(var+eps); w = bnw/std; b = bnb - w*mean
//   l_j = rint(((j+0.5)*alpha2 - b) / (alpha1*w));  t0 = l_0, diff = l_1 - l_0
// ---------------------------------------------------------------------------
__global__ void prep_kernel(const float* __restrict__ w1, const float* __restrict__ w2,
                            const float* __restrict__ bn1w, const float* __restrict__ bn1b,
                            const float* __restrict__ bn1m, const float* __restrict__ bn1v,
                            const float* __restrict__ bn2w, const float* __restrict__ bn2b,
                            const float* __restrict__ bn2m, const float* __restrict__ bn2v,
                            const float* __restrict__ a1p, const float* __restrict__ a2p,
                            const float* __restrict__ nsp)
{
    __shared__ float mean1[32], mean2[32];
    int t = threadIdx.x;
    if (t < 32) {
        float s = 0.f;
        for (int i = 0; i < 288; i++) s += w1[t*288 + i];
        mean1[t] = s / 288.f;
    } else if (t < 64) {
        int c = t - 32;
        float s = 0.f;
        for (int i = 0; i < 288; i++) s += w2[c*288 + i];
        mean2[c] = s / 288.f;
    }
    __syncthreads();

    // signs: source index idx = co*288 + (ci*9 + tap); dest = (ci*9+tap)*32 + co
    for (int idx = t; idx < 9216; idx += blockDim.x) {
        int co = idx / 288;
        int r  = idx % 288;
        int dst = r * 32 + co;
        g_s1[dst] = (w1[idx] > mean1[co]) ? 1.f : -1.f;
        g_s2[dst] = (w2[idx] > mean2[co]) ? 1.f : -1.f;
    }

    if (t < 32) {
        float a1 = *a1p, a2 = *a2p, ns = *nsp;
        {
            float sd = sqrtf(bn1v[t] + 1e-5f);
            float w  = bn1w[t] / sd;
            float b  = bn1b[t] - w * bn1m[t];
            float l0 = rintf((0.5f*a2 - b) / (a1*w));
            float l1 = rintf((1.5f*a2 - b) / (a1*w));
            g_lut1[t]      = l0;
            g_lut1[32 + t] = l1 - l0;
        }
        {
            float sd = sqrtf(bn2v[t] + 1e-5f);
            float w  = bn2w[t] / sd;
            float b  = bn2b[t] - w * bn2m[t];
            float l0 = rintf((0.5f*ns - b) / (a2*w));
            float l1 = rintf((1.5f*ns - b) / (a2*w));
            g_lut2[t]      = l0;
            g_lut2[32 + t] = l1 - l0;
        }
    }
}

// ---------------------------------------------------------------------------
// Fused conv3x3(pad=1, stride=1, ±1 weights) + LUT quantize.
// STAGE 0: input = float x (kernel arg), output = uint8 levels (g_h1)
// STAGE 1: input = uint8 levels (g_h1 device global), output = float (d_out)
//
// Block: 256 threads = 2 output rows x 128 x-slots (112 active).
// Tile: 32ch x 4 rows x 114 cols of fp32 in SMEM + 9216 sign floats
// laid out [ci][tap][co] so the co-loop reads broadcast float4s (LDS stays
// far below the fma pipe). Each thread holds 32 fp32 accumulators.
// ---------------------------------------------------------------------------
template<int STAGE>
__global__ __launch_bounds__(256, 2)
void conv_lut_kernel(const float* __restrict__ inptr, float* __restrict__ outptr)
{
    extern __shared__ float sm[];
    float* in_s = sm;               // 32*4*114 = 14592 floats
    float* sw   = sm + 14592;       // 9216 floats
    float* lt   = sm + 23808;       // 64 floats

    const int tid = threadIdx.x;
    const int xh = blockIdx.x;      // 0..1
    const int yp = blockIdx.y;      // 0..111
    const int b  = blockIdx.z;      // 0..15
    const int y0 = yp * 2;
    const int x0 = xh * 112;

    // stage signs + lut into smem
    {
        const float* gs = (STAGE == 0) ? g_s1 : g_s2;
        for (int i = tid; i < 9216; i += 256) sw[i] = gs[i];
        const float* gl = (STAGE == 0) ? g_lut1 : g_lut2;
        if (tid < 64) lt[tid] = gl[tid];
    }

    // load input tile (rows y0-1..y0+2, cols x0-1..x0+112), zero-padded.
    // STAGE 0 reads the fp32 input tensor; STAGE 1 reads the uint8 level
    // scratch g_h1 (device global — NOT the kernel argument).
    for (int i = tid; i < 14592; i += 256) {
        int ci  = i / 456;
        int r   = i % 456;
        int row = r / 114;
        int col = r % 114;
        int gy = y0 - 1 + row;
        int gx = x0 - 1 + col;
        float v = 0.f;
        if (gy >= 0 && gy < HH && gx >= 0 && gx < WW) {
            int off = ((b*CC + ci)*HH + gy)*WW + gx;
            if (STAGE == 0) v = inptr[off];
            else            v = (float)g_h1[off];
        }
        in_s[i] = v;
    }
    __syncthreads();

    const int tx = tid & 127;
    const int ty = tid >> 7;
    if (tx < 112) {
        float acc[32];
        #pragma unroll
        for (int i = 0; i < 32; i++) acc[i] = 0.f;

        for (int ci = 0; ci < 32; ci++) {
            #pragma unroll
            for (int dy = 0; dy < 3; dy++) {
                const float* r = in_s + ci*456 + (ty + dy)*114 + tx;
                float v0 = r[0], v1 = r[1], v2 = r[2];
                const float4* s4 = (const float4*)(sw + (ci*9 + dy*3)*32);
                #pragma unroll
                for (int q = 0; q < 8; q++) {
                    float4 a  = s4[q];        // dx = 0
                    float4 bq = s4[8 + q];    // dx = 1
                    float4 c  = s4[16 + q];   // dx = 2
                    acc[4*q+0] += a.x*v0 + bq.x*v1 + c.x*v2;
                    acc[4*q+1] += a.y*v0 + bq.y*v1 + c.y*v2;
                    acc[4*q+2] += a.z*v0 + bq.z*v1 + c.z*v2;
                    acc[4*q+3] += a.w*v0 + bq.w*v1 + c.w*v2;
                }
            }
        }

        const int y = y0 + ty;
        const int x = x0 + tx;
        #pragma unroll
        for (int co = 0; co < 32; co++) {
            float t0 = lt[co];
            float df = lt[32 + co];
            float v  = acc[co];
            int lev = 0;
            #pragma unroll
            for (int j = 0; j < 7; j++) {
                float th = t0 + (float)j * df;
                // even j: strict '>', odd j: '>=' (matches reference chain)
                lev += (j & 1) ? (v >= th) : (v > th);
            }
            int off = ((b*CC + co)*HH + y)*WW + x;
            if (STAGE == 0) g_h1[off] = (unsigned char)lev;
            else            outptr[off] = (float)lev;
        }
    }
}

// ---------------------------------------------------------------------------
extern "C" void kernel_launch(void* const* d_in, const int* in_sizes, int n_in,
                              void* d_out, int out_size)
{
    const float* x    = (const float*)d_in[0];
    const float* w1   = (const float*)d_in[1];
    const float* w2   = (const float*)d_in[2];
    const float* bn1w = (const float*)d_in[3];
    const float* bn1b = (const float*)d_in[4];
    const float* bn1m = (const float*)d_in[5];
    const float* bn1v = (const float*)d_in[6];
    const float* bn2w = (const float*)d_in[7];
    const float* bn2b = (const float*)d_in[8];
    const float* bn2m = (const float*)d_in[9];
    const float* bn2v = (const float*)d_in[10];
    const float* a1   = (const float*)d_in[11];
    const float* a2   = (const float*)d_in[12];
    const float* ns   = (const float*)d_in[13];

    prep_kernel<<<1, 256>>>(w1, w2, bn1w, bn1b, bn1m, bn1v,
                            bn2w, bn2b, bn2m, bn2v, a1, a2, ns);

    const size_t smem = 23872 * sizeof(float);  // 95488 B
    cudaFuncSetAttribute(conv_lut_kernel<0>, cudaFuncAttributeMaxDynamicSharedMemorySize, (int)smem);
    cudaFuncSetAttribute(conv_lut_kernel<1>, cudaFuncAttributeMaxDynamicSharedMemorySize, (int)smem);

    dim3 grid(2, 112, 16);
    conv_lut_kernel<0><<<grid, 256, smem>>>(x, nullptr);
    conv_lut_kernel<1><<<grid, 256, smem>>>(nullptr, (float*)d_out);
}

// round 11
// speedup vs baseline: 1.7916x; 1.7916x over previous
#include <cuda_runtime.h>
#include <cuda_bf16.h>
#include <math.h>
#include <stdint.h>

#define BB 16
#define CC 32
#define HH 224
#define WW 224
#define NPIX (HH*WW)            // 50176
#define CL_PLANE (NPIX*CC)      // channel-last elems per batch
#define NTILES (BB*HH*2)        // 7168 tiles (y rows x two x-halves)

#define KP 296                  // padded K pitch (288 + 8), elems
#define LUT_OFF 0               // 64 floats
#define B_OFF 256               // 32*296*2 = 18944 B
#define A_OFF 19456             // 128*296*2 = 75776 B (16-aligned)
#define SMEM_BYTES 95232        // fits 2 CTAs/SM (190464 <= 228KB)
#define DF_PITCH 132            // fp32 bounce pitch (bank-conflict-free)

// ---------------- device scratch (static: allowed) ----------------
__device__ unsigned short g_hx[BB*CL_PLANE];   // x split hi  (channel-last bf16)
__device__ unsigned short g_mx[BB*CL_PLANE];   //         mid
__device__ unsigned short g_lx[BB*CL_PLANE];   //         lo
__device__ unsigned short g_lev[BB*CL_PLANE];  // stage-0 levels, channel-last bf16
__device__ unsigned short g_B1[CC*288];        // conv1 signs, [co][k], k=tap*32+ci
__device__ unsigned short g_B2[CC*288];        // conv2 signs
__device__ float g_lut1[64];                   // t0[32], diff[32]
__device__ float g_lut2[64];

// ---------------------------------------------------------------------------
// Prep: per-channel weight means -> sign(+-1) bf16 B operands [co][k], and
// BN-folded LUT thresholds (t0, diff) per channel.
// ---------------------------------------------------------------------------
__global__ void prep_kernel(const float* __restrict__ w1, const float* __restrict__ w2,
                            const float* __restrict__ bn1w, const float* __restrict__ bn1b,
                            const float* __restrict__ bn1m, const float* __restrict__ bn1v,
                            const float* __restrict__ bn2w, const float* __restrict__ bn2b,
                            const float* __restrict__ bn2m, const float* __restrict__ bn2v,
                            const float* __restrict__ a1p, const float* __restrict__ a2p,
                            const float* __restrict__ nsp)
{
    __shared__ float mean1[32], mean2[32];
    int t = threadIdx.x;
    if (t < 32) {
        float s = 0.f;
        for (int i = 0; i < 288; i++) s += w1[t*288 + i];
        mean1[t] = s / 288.f;
    } else if (t < 64) {
        int c = t - 32;
        float s = 0.f;
        for (int i = 0; i < 288; i++) s += w2[c*288 + i];
        mean2[c] = s / 288.f;
    }
    __syncthreads();

    // weight idx = co*288 + ci*9 + tap  ->  B[co][k], k = tap*32 + ci
    for (int idx = t; idx < 9216; idx += blockDim.x) {
        int co  = idx / 288;
        int r   = idx % 288;
        int ci  = r / 9;
        int tap = r % 9;
        int k   = tap*32 + ci;
        g_B1[co*288 + k] = (w1[idx] > mean1[co]) ? 0x3F80 : 0xBF80;
        g_B2[co*288 + k] = (w2[idx] > mean2[co]) ? 0x3F80 : 0xBF80;
    }

    if (t < 32) {
        float a1 = *a1p, a2 = *a2p, ns = *nsp;
        {
            float sd = sqrtf(bn1v[t] + 1e-5f);
            float w  = bn1w[t] / sd;
            float b  = bn1b[t] - w * bn1m[t];
            float l0 = rintf((0.5f*a2 - b) / (a1*w));
            float l1 = rintf((1.5f*a2 - b) / (a1*w));
            g_lut1[t]      = l0;
            g_lut1[32 + t] = l1 - l0;
        }
        {
            float sd = sqrtf(bn2v[t] + 1e-5f);
            float w  = bn2w[t] / sd;
            float b  = bn2b[t] - w * bn2m[t];
            float l0 = rintf((0.5f*ns - b) / (a2*w));
            float l1 = rintf((1.5f*ns - b) / (a2*w));
            g_lut2[t]      = l0;
            g_lut2[32 + t] = l1 - l0;
        }
    }
}

// ---------------------------------------------------------------------------
// Prepass: x (fp32, NCHW) -> exact 3-way bf16 split (h+m+l reconstructs x),
// channel-last [b][y][x][ci] for 64B-contiguous im2col reads.
// ---------------------------------------------------------------------------
__global__ void split_kernel(const float* __restrict__ x)
{
    __shared__ float sh[32*225];
    int blk = blockIdx.x;
    int b = blk / HH, y = blk % HH;
    int t = threadIdx.x;

    const float* src = x + (size_t)(b*CC)*NPIX + y*WW;
    for (int i = t; i < CC*WW; i += 256) {
        int ci = i / WW, xx = i % WW;
        sh[ci*225 + xx] = src[(size_t)ci*NPIX + xx];
    }
    __syncthreads();

    size_t obase = (size_t)(b*HH + y) * (WW*CC);
    for (int j = t; j < WW*CC; j += 256) {
        int ci = j & 31, xx = j >> 5;
        float v = sh[ci*225 + xx];
        __nv_bfloat16 h = __float2bfloat16(v);
        float r = v - __bfloat162float(h);
        __nv_bfloat16 m = __float2bfloat16(r);
        float r2 = r - __bfloat162float(m);
        __nv_bfloat16 l = __float2bfloat16(r2);
        g_hx[obase + j] = ((__nv_bfloat16_raw)h).x;
        g_mx[obase + j] = ((__nv_bfloat16_raw)m).x;
        g_lx[obase + j] = ((__nv_bfloat16_raw)l).x;
    }
}

// ---------------------------------------------------------------------------
// mma.sync helpers (baseline PTX, works on compute_103 family target)
// ---------------------------------------------------------------------------
// Chained form: D = A*B + D  (used in stage 1, exact-integer arithmetic).
__device__ __forceinline__ void mma16816(float& d0, float& d1, float& d2, float& d3,
                                         uint32_t a0, uint32_t a1, uint32_t a2, uint32_t a3,
                                         uint32_t b0, uint32_t b1)
{
    asm volatile(
        "mma.sync.aligned.m16n8k16.row.col.f32.bf16.bf16.f32 "
        "{%0,%1,%2,%3}, {%4,%5,%6,%7}, {%8,%9}, {%0,%1,%2,%3};"
        : "+f"(d0), "+f"(d1), "+f"(d2), "+f"(d3)
        : "r"(a0), "r"(a1), "r"(a2), "r"(a3), "r"(b0), "r"(b1));
}
// Zero-C form + RN FADD fold: avoids tensor-core accumulator-carry truncation
// on the large stage-0 accumulator. Each k=16 chunk sum is (near-)exact; the
// cross-chunk chain is then IEEE RN fp32, matching the FFMA-baseline error.
__device__ __forceinline__ void mma16816_zc(float& s0, float& s1, float& s2, float& s3,
                                            uint32_t a0, uint32_t a1, uint32_t a2, uint32_t a3,
                                            uint32_t b0, uint32_t b1)
{
    float d0 = 0.f, d1 = 0.f, d2 = 0.f, d3 = 0.f;
    asm volatile(
        "mma.sync.aligned.m16n8k16.row.col.f32.bf16.bf16.f32 "
        "{%0,%1,%2,%3}, {%4,%5,%6,%7}, {%8,%9}, {%0,%1,%2,%3};"
        : "+f"(d0), "+f"(d1), "+f"(d2), "+f"(d3)
        : "r"(a0), "r"(a1), "r"(a2), "r"(a3), "r"(b0), "r"(b1));
    s0 += d0; s1 += d1; s2 += d2; s3 += d3;
}

__device__ __forceinline__ int lut_level(float v, float t0, float df) {
    int lev = 0;
    float th = t0;
    #pragma unroll
    for (int j = 0; j < 7; j++) {
        lev += (j & 1) ? (v >= th) : (v > th);   // validated compare chain
        th += df;
    }
    return lev;
}
__device__ __forceinline__ unsigned int bf16bits_of_int(int lev) {
    __nv_bfloat16 h = __float2bfloat16((float)lev);   // 0..7 exact
    return (unsigned int)((__nv_bfloat16_raw)h).x;
}

// ---------------------------------------------------------------------------
// Persistent fused conv3x3(pad=1, +-1 weights) + LUT via mma.sync bf16 HMMA.
//   tile = 128 pixels of one image row (x0 in {0,96}; overlap region computes
//   identical values), N=32 co, K=288.
// STAGE 0: A from g_hx/g_mx/g_lx (3 register-accumulating passes, zero-C
//          HMMA + RN FADD folds), -> g_lev.
// STAGE 1: A from g_lev (1 chained pass, exact), -> d_out fp32 NCHW bounce.
// 8 warps: warp w owns M-strip rows [16w, 16w+16). Accumulators in registers.
// ---------------------------------------------------------------------------
template<int STAGE>
__global__ __launch_bounds__(256, 2)
void conv_mma_kernel(float* __restrict__ outp)
{
    extern __shared__ char smc[];
    float*          lut = (float*)(smc + LUT_OFF);
    unsigned short* Bs  = (unsigned short*)(smc + B_OFF);
    unsigned short* As  = (unsigned short*)(smc + A_OFF);
    float*          Df  = (float*)(smc + A_OFF);     // stage-1 bounce (reuses A)

    const int tid   = threadIdx.x;
    const int wid   = tid >> 5;
    const int lane  = tid & 31;
    const int g     = lane >> 2;       // groupID (row / n)
    const int tg    = lane & 3;        // threadID_in_group (col pair)

    // stage B + LUT into smem
    {
        const uint32_t* gb = (const uint32_t*)(STAGE == 0 ? g_B1 : g_B2);
        uint32_t* bs32 = (uint32_t*)Bs;
        for (int i = tid; i < 32*144; i += 256) {
            int co = i / 144, j = i % 144;
            bs32[co*(KP/2) + j] = gb[co*144 + j];
        }
        const float* gl = (STAGE == 0) ? g_lut1 : g_lut2;
        if (tid < 64) lut[tid] = gl[tid];
    }
    __syncthreads();

    // per-lane LUT regs: co(nt,i) = nt*8 + 2*tg + i
    float t0r[8], dfr[8];
    #pragma unroll
    for (int nt = 0; nt < 4; nt++) {
        #pragma unroll
        for (int i = 0; i < 2; i++) {
            int co = nt*8 + 2*tg + i;
            t0r[nt*2+i] = lut[co];
            dfr[nt*2+i] = lut[32+co];
        }
    }

    const int p    = tid & 127;        // pixel (A row) this thread builds
    const int half = tid >> 7;
    const int tap_lo = half ? 5 : 0;
    const int tap_hi = half ? 9 : 5;

    for (int t = blockIdx.x; t < NTILES; t += gridDim.x) {
        const int b  = t / (HH*2);
        const int rr = t % (HH*2);
        const int y  = rr >> 1;
        const int x0 = (rr & 1) * 96;
        const int nsub = (STAGE == 0) ? 3 : 1;

        float acc[4][4];
        #pragma unroll
        for (int nt = 0; nt < 4; nt++)
            #pragma unroll
            for (int c = 0; c < 4; c++) acc[nt][c] = 0.f;

        for (int sub = 0; sub < nsub; sub++) {
            const unsigned short* src;
            if (STAGE == 0) src = (sub == 0) ? g_hx : (sub == 1) ? g_mx : g_lx;
            else            src = g_lev;
            const unsigned short* srcb = src + (size_t)b * CL_PLANE;

            // ---- im2col build: A[p][tap*32 .. +32] (64B, 4x STS.128) ----
            for (int tap = tap_lo; tap < tap_hi; tap++) {
                int gy = y  + tap/3 - 1;
                int gx = x0 + p + (tap % 3) - 1;
                uint4 v0 = make_uint4(0,0,0,0), v1 = v0, v2 = v0, v3 = v0;
                if ((unsigned)gy < HH && (unsigned)gx < WW) {
                    const uint4* q = (const uint4*)(srcb + (((size_t)gy*WW + gx) << 5));
                    v0 = q[0]; v1 = q[1]; v2 = q[2]; v3 = q[3];
                }
                uint4* dst = (uint4*)(As + p*KP + tap*32);
                dst[0] = v0; dst[1] = v1; dst[2] = v2; dst[3] = v3;
            }
            __syncthreads();

            // ---- 18 k-steps of m16n8k16 ----
            const unsigned short* Aw = As + wid*16*KP;
            #pragma unroll
            for (int s = 0; s < 18; s++) {
                const int k = s*16;
                uint32_t a0 = *(const uint32_t*)(Aw + (g   )*KP + k + 2*tg);
                uint32_t a1 = *(const uint32_t*)(Aw + (g+8 )*KP + k + 2*tg);
                uint32_t a2 = *(const uint32_t*)(Aw + (g   )*KP + k + 2*tg + 8);
                uint32_t a3 = *(const uint32_t*)(Aw + (g+8 )*KP + k + 2*tg + 8);
                #pragma unroll
                for (int nt = 0; nt < 4; nt++) {
                    uint32_t b0 = *(const uint32_t*)(Bs + (nt*8+g)*KP + k + 2*tg);
                    uint32_t b1 = *(const uint32_t*)(Bs + (nt*8+g)*KP + k + 2*tg + 8);
                    if (STAGE == 0) {
                        // zero-C + RN FADD fold: FFMA-class rounding
                        mma16816_zc(acc[nt][0], acc[nt][1], acc[nt][2], acc[nt][3],
                                    a0, a1, a2, a3, b0, b1);
                    } else {
                        // exact integer arithmetic: chained accumulate is free
                        mma16816(acc[nt][0], acc[nt][1], acc[nt][2], acc[nt][3],
                                 a0, a1, a2, a3, b0, b1);
                    }
                }
            }
            __syncthreads();   // all warps done reading A before next build
        }

        // ---- epilogue: LUT levels from register accumulators ----
        const int p0 = wid*16 + g;     // D rows for c0/c1
        const int p1 = p0 + 8;         // D rows for c2/c3
        if (STAGE == 0) {
            size_t base0 = (size_t)b*CL_PLANE + (((size_t)y*WW + x0 + p0) << 5);
            size_t base1 = (size_t)b*CL_PLANE + (((size_t)y*WW + x0 + p1) << 5);
            #pragma unroll
            for (int nt = 0; nt < 4; nt++) {
                int l00 = lut_level(acc[nt][0], t0r[nt*2+0], dfr[nt*2+0]);
                int l01 = lut_level(acc[nt][1], t0r[nt*2+1], dfr[nt*2+1]);
                int l10 = lut_level(acc[nt][2], t0r[nt*2+0], dfr[nt*2+0]);
                int l11 = lut_level(acc[nt][3], t0r[nt*2+1], dfr[nt*2+1]);
                *(uint32_t*)(g_lev + base0 + nt*8 + 2*tg) =
                    bf16bits_of_int(l00) | (bf16bits_of_int(l01) << 16);
                *(uint32_t*)(g_lev + base1 + nt*8 + 2*tg) =
                    bf16bits_of_int(l10) | (bf16bits_of_int(l11) << 16);
            }
            // epilogue touches no smem -> next tile's build is safe after the
            // post-k-loop __syncthreads already executed above
        } else {
            // bounce through smem as [co][DF_PITCH] for coalesced NCHW stores
            #pragma unroll
            for (int nt = 0; nt < 4; nt++) {
                int c0 = nt*8 + 2*tg, c1 = c0 + 1;
                Df[c0*DF_PITCH + p0] = (float)lut_level(acc[nt][0], t0r[nt*2+0], dfr[nt*2+0]);
                Df[c1*DF_PITCH + p0] = (float)lut_level(acc[nt][1], t0r[nt*2+1], dfr[nt*2+1]);
                Df[c0*DF_PITCH + p1] = (float)lut_level(acc[nt][2], t0r[nt*2+0], dfr[nt*2+0]);
                Df[c1*DF_PITCH + p1] = (float)lut_level(acc[nt][3], t0r[nt*2+1], dfr[nt*2+1]);
            }
            __syncthreads();
            {
                int co = tid >> 3, ch = tid & 7;
                int px = ch * 16;
                const uint4* s4 = (const uint4*)(Df + co*DF_PITCH + px);
                uint4* o4 = (uint4*)(outp + (size_t)b*(CC*NPIX) + (size_t)co*NPIX
                                          + (size_t)y*WW + x0 + px);
                o4[0] = s4[0]; o4[1] = s4[1]; o4[2] = s4[2]; o4[3] = s4[3];
            }
            __syncthreads();   // Df region becomes A again next tile
        }
    }
}

// ---------------------------------------------------------------------------
extern "C" void kernel_launch(void* const* d_in, const int* in_sizes, int n_in,
                              void* d_out, int out_size)
{
    const float* x    = (const float*)d_in[0];
    const float* w1   = (const float*)d_in[1];
    const float* w2   = (const float*)d_in[2];
    const float* bn1w = (const float*)d_in[3];
    const float* bn1b = (const float*)d_in[4];
    const float* bn1m = (const float*)d_in[5];
    const float* bn1v = (const float*)d_in[6];
    const float* bn2w = (const float*)d_in[7];
    const float* bn2b = (const float*)d_in[8];
    const float* bn2m = (const float*)d_in[9];
    const float* bn2v = (const float*)d_in[10];
    const float* a1   = (const float*)d_in[11];
    const float* a2   = (const float*)d_in[12];
    const float* ns   = (const float*)d_in[13];

    prep_kernel<<<1, 256>>>(w1, w2, bn1w, bn1b, bn1m, bn1v,
                            bn2w, bn2b, bn2m, bn2v, a1, a2, ns);
    split_kernel<<<BB*HH, 256>>>(x);

    cudaFuncSetAttribute(conv_mma_kernel<0>, cudaFuncAttributeMaxDynamicSharedMemorySize, SMEM_BYTES);
    cudaFuncSetAttribute(conv_mma_kernel<1>, cudaFuncAttributeMaxDynamicSharedMemorySize, SMEM_BYTES);

    conv_mma_kernel<0><<<296, 256, SMEM_BYTES>>>(nullptr);
    conv_mma_kernel<1><<<296, 256, SMEM_BYTES>>>((float*)d_out);
}

// round 14
// speedup vs baseline: 1.8390x; 1.0265x over previous
#include <cuda_runtime.h>
#include <cuda_bf16.h>
#include <math.h>
#include <stdint.h>

#define BB 16
#define CC 32
#define HH 224
#define WW 224
#define NPIX (HH*WW)            // 50176
#define CL_PLANE (NPIX*CC)      // channel-last elems per batch
#define NTILES (BB*HH*2)        // 7168 tiles (y rows x two x-halves)

#define KP 296                  // padded K pitch (288+8) elems; 148 words = 20 mod 32 -> ldsm conflict-free
#define LUT_OFF 0               // 64 floats
#define B_OFF 256               // 32*296*2 = 18944 B
#define A_OFF 19456             // 128*296*2 = 75776 B (16-aligned)
#define SMEM_BYTES 95232        // fits 2 CTAs/SM (190464 <= 228KB)
#define DF_PITCH 132            // fp32 bounce pitch (bank-conflict-free)

// ---------------- device scratch (static: allowed) ----------------
__device__ unsigned short g_hx[BB*CL_PLANE];   // x split hi  (channel-last bf16)
__device__ unsigned short g_mx[BB*CL_PLANE];   //         mid
__device__ unsigned short g_lx[BB*CL_PLANE];   //         lo
__device__ unsigned short g_lev[BB*CL_PLANE];  // stage-0 levels, channel-last bf16
__device__ unsigned short g_B1[CC*288];        // conv1 signs, [co][k], k=tap*32+ci
__device__ unsigned short g_B2[CC*288];        // conv2 signs
__device__ float g_lut1[64];                   // t0[32], diff[32]
__device__ float g_lut2[64];

// ---------------------------------------------------------------------------
// Prep (unchanged, validated): signs [co][k] + BN-folded LUT (t0, diff).
// ---------------------------------------------------------------------------
__global__ void prep_kernel(const float* __restrict__ w1, const float* __restrict__ w2,
                            const float* __restrict__ bn1w, const float* __restrict__ bn1b,
                            const float* __restrict__ bn1m, const float* __restrict__ bn1v,
                            const float* __restrict__ bn2w, const float* __restrict__ bn2b,
                            const float* __restrict__ bn2m, const float* __restrict__ bn2v,
                            const float* __restrict__ a1p, const float* __restrict__ a2p,
                            const float* __restrict__ nsp)
{
    __shared__ float mean1[32], mean2[32];
    int t = threadIdx.x;
    if (t < 32) {
        float s = 0.f;
        for (int i = 0; i < 288; i++) s += w1[t*288 + i];
        mean1[t] = s / 288.f;
    } else if (t < 64) {
        int c = t - 32;
        float s = 0.f;
        for (int i = 0; i < 288; i++) s += w2[c*288 + i];
        mean2[c] = s / 288.f;
    }
    __syncthreads();

    for (int idx = t; idx < 9216; idx += blockDim.x) {
        int co  = idx / 288;
        int r   = idx % 288;
        int ci  = r / 9;
        int tap = r % 9;
        int k   = tap*32 + ci;
        g_B1[co*288 + k] = (w1[idx] > mean1[co]) ? 0x3F80 : 0xBF80;
        g_B2[co*288 + k] = (w2[idx] > mean2[co]) ? 0x3F80 : 0xBF80;
    }

    if (t < 32) {
        float a1 = *a1p, a2 = *a2p, ns = *nsp;
        {
            float sd = sqrtf(bn1v[t] + 1e-5f);
            float w  = bn1w[t] / sd;
            float b  = bn1b[t] - w * bn1m[t];
            float l0 = rintf((0.5f*a2 - b) / (a1*w));
            float l1 = rintf((1.5f*a2 - b) / (a1*w));
            g_lut1[t]      = l0;
            g_lut1[32 + t] = l1 - l0;
        }
        {
            float sd = sqrtf(bn2v[t] + 1e-5f);
            float w  = bn2w[t] / sd;
            float b  = bn2b[t] - w * bn2m[t];
            float l0 = rintf((0.5f*ns - b) / (a2*w));
            float l1 = rintf((1.5f*ns - b) / (a2*w));
            g_lut2[t]      = l0;
            g_lut2[32 + t] = l1 - l0;
        }
    }
}

// ---------------------------------------------------------------------------
// Prepass (unchanged, validated): x -> exact 3-way bf16 split, channel-last.
// ---------------------------------------------------------------------------
__global__ void split_kernel(const float* __restrict__ x)
{
    __shared__ float sh[32*225];
    int blk = blockIdx.x;
    int b = blk / HH, y = blk % HH;
    int t = threadIdx.x;

    const float* src = x + (size_t)(b*CC)*NPIX + y*WW;
    for (int i = t; i < CC*WW; i += 256) {
        int ci = i / WW, xx = i % WW;
        sh[ci*225 + xx] = src[(size_t)ci*NPIX + xx];
    }
    __syncthreads();

    size_t obase = (size_t)(b*HH + y) * (WW*CC);
    for (int j = t; j < WW*CC; j += 256) {
        int ci = j & 31, xx = j >> 5;
        float v = sh[ci*225 + xx];
        __nv_bfloat16 h = __float2bfloat16(v);
        float r = v - __bfloat162float(h);
        __nv_bfloat16 m = __float2bfloat16(r);
        float r2 = r - __bfloat162float(m);
        __nv_bfloat16 l = __float2bfloat16(r2);
        g_hx[obase + j] = ((__nv_bfloat16_raw)h).x;
        g_mx[obase + j] = ((__nv_bfloat16_raw)m).x;
        g_lx[obase + j] = ((__nv_bfloat16_raw)l).x;
    }
}

// ---------------------------------------------------------------------------
// PTX helpers (baseline PTX: sm_75/sm_80 features, fine on compute_103)
// ---------------------------------------------------------------------------
__device__ __forceinline__ uint32_t s2u(const void* p) {
    uint32_t a;
    asm("{ .reg .u64 t; cvta.to.shared.u64 t, %1; cvt.u32.u64 %0, t; }" : "=r"(a) : "l"(p));
    return a;
}
__device__ __forceinline__ void ldsm4(uint32_t* r, uint32_t addr) {
    asm volatile("ldmatrix.sync.aligned.m8n8.x4.shared.b16 {%0,%1,%2,%3}, [%4];"
                 : "=r"(r[0]), "=r"(r[1]), "=r"(r[2]), "=r"(r[3]) : "r"(addr));
}
// d += a*b (fragment MMA, accumulate into given float4)
__device__ __forceinline__ void mma_acc(float* d, const uint32_t* a, uint32_t b0, uint32_t b1) {
    asm volatile(
        "mma.sync.aligned.m16n8k16.row.col.f32.bf16.bf16.f32 "
        "{%0,%1,%2,%3}, {%4,%5,%6,%7}, {%8,%9}, {%0,%1,%2,%3};"
        : "+f"(d[0]), "+f"(d[1]), "+f"(d[2]), "+f"(d[3])
        : "r"(a[0]), "r"(a[1]), "r"(a[2]), "r"(a[3]), "r"(b0), "r"(b1));
}
__device__ __forceinline__ int lut_level(float v, float t0, float df) {
    int lev = 0;
    float th = t0;
    #pragma unroll
    for (int j = 0; j < 7; j++) {
        lev += (j & 1) ? (v >= th) : (v > th);   // validated compare chain
        th += df;
    }
    return lev;
}
__device__ __forceinline__ unsigned int bf16bits_of_int(int lev) {
    __nv_bfloat16 h = __float2bfloat16((float)lev);   // 0..7 exact
    return (unsigned int)((__nv_bfloat16_raw)h).x;
}

// ---------------------------------------------------------------------------
// Persistent fused conv3x3(pad=1, +-1 weights) + LUT via mma.sync bf16 HMMA.
// EXACT R11 structure (tile = 1 row x 128 px, x0 in {0,96}; warp w owns
// pixels [16w,16w+16); im2col build LDG+STS; same barriers/epilogue).
// Deltas vs R11: (a) ldmatrix.x4 fragment loads on the SAME A/B layouts
// (element-identical to R11's scalar loads); (b) stage-0 pair-fold: chain 2
// k-steps in the tensor core, RN-fold per pair (halves FADDs; error class
// unchanged). Stage 1 fully chained (exact integers), as in R11.
// ---------------------------------------------------------------------------
template<int STAGE>
__global__ __launch_bounds__(256, 2)
void conv_mma_kernel(float* __restrict__ outp)
{
    extern __shared__ char smc[];
    float*          lut = (float*)(smc + LUT_OFF);
    unsigned short* Bs  = (unsigned short*)(smc + B_OFF);
    unsigned short* As  = (unsigned short*)(smc + A_OFF);
    float*          Df  = (float*)(smc + A_OFF);     // stage-1 bounce (reuses A)

    const int tid   = threadIdx.x;
    const int wid   = tid >> 5;
    const int lane  = tid & 31;
    const int g     = lane >> 2;       // groupID (row / n)
    const int tg    = lane & 3;        // threadID_in_group (col pair)

    // stage B + LUT into smem (verbatim R11)
    {
        const uint32_t* gb = (const uint32_t*)(STAGE == 0 ? g_B1 : g_B2);
        uint32_t* bs32 = (uint32_t*)Bs;
        for (int i = tid; i < 32*144; i += 256) {
            int co = i / 144, j = i - co*144;
            bs32[co*(KP/2) + j] = gb[co*144 + j];
        }
        const float* gl = (STAGE == 0) ? g_lut1 : g_lut2;
        if (tid < 64) lut[tid] = gl[tid];
    }
    __syncthreads();

    // per-lane LUT regs: co(nt,i) = nt*8 + 2*tg + i  (verbatim R11)
    float t0r[8], dfr[8];
    #pragma unroll
    for (int nt = 0; nt < 4; nt++) {
        #pragma unroll
        for (int i = 0; i < 2; i++) {
            int co = nt*8 + 2*tg + i;
            t0r[nt*2+i] = lut[co];
            dfr[nt*2+i] = lut[32+co];
        }
    }

    // ldmatrix lane-address setup.
    // A [p][KP]: matrices (pix 0-7,k+0)(pix 8-15,k+0)(pix 0-7,k+8)(pix 8-15,k+8)
    //   -> frag r0..r3 = R11's a0..a3.
    // B [co][KP]: matrices (co 0-7,k+0)(co 0-7,k+8)(co 8-15,k+0)(co 8-15,k+8)
    //   -> per ldsm4: r0,r1 = b0,b1 of even nt; r2,r3 = b0,b1 of odd nt.
    const uint32_t sbA = s2u(As);
    const uint32_t sbB = s2u(Bs);
    const uint32_t abase = sbA
        + (uint32_t)((wid*16 + (lane & 15))*KP + ((lane >> 4) * 8)) * 2;
    const int nrow = (lane & 7) + ((lane >> 4) << 3);
    const uint32_t bbase0 = sbB + (uint32_t)(nrow*KP + (((lane >> 3) & 1) * 8)) * 2;
    const uint32_t bbase1 = bbase0 + (uint32_t)(16*KP*2);

    const int p    = tid & 127;        // pixel (A row) this thread builds
    const int half = tid >> 7;
    const int tap_lo = half ? 5 : 0;
    const int tap_hi = half ? 9 : 5;

    for (int t = blockIdx.x; t < NTILES; t += gridDim.x) {
        const int b  = t / (HH*2);
        const int rr = t % (HH*2);
        const int y  = rr >> 1;
        const int x0 = (rr & 1) * 96;
        const int nsub = (STAGE == 0) ? 3 : 1;

        float acc[4][4];
        #pragma unroll
        for (int nt = 0; nt < 4; nt++)
            #pragma unroll
            for (int c = 0; c < 4; c++) acc[nt][c] = 0.f;

        for (int sub = 0; sub < nsub; sub++) {
            const unsigned short* src;
            if (STAGE == 0) src = (sub == 0) ? g_hx : (sub == 1) ? g_mx : g_lx;
            else            src = g_lev;
            const unsigned short* srcb = src + (size_t)b * CL_PLANE;

            // ---- im2col build (verbatim R11): A[p][tap*32 .. +32] ----
            for (int tap = tap_lo; tap < tap_hi; tap++) {
                int gy = y  + tap/3 - 1;
                int gx = x0 + p + (tap % 3) - 1;
                uint4 v0 = make_uint4(0,0,0,0), v1 = v0, v2 = v0, v3 = v0;
                if ((unsigned)gy < HH && (unsigned)gx < WW) {
                    const uint4* q = (const uint4*)(srcb + (((size_t)gy*WW + gx) << 5));
                    v0 = q[0]; v1 = q[1]; v2 = q[2]; v3 = q[3];
                }
                uint4* dst = (uint4*)(As + p*KP + tap*32);
                dst[0] = v0; dst[1] = v1; dst[2] = v2; dst[3] = v3;
            }
            __syncthreads();

            // ---- 18 k-steps as 9 pairs of m16n8k16 (ldmatrix fragments) ----
            #pragma unroll
            for (int sp = 0; sp < 9; sp++) {
                const uint32_t o0 = (uint32_t)(2*sp)     * 32;  // k-step byte offsets
                const uint32_t o1 = (uint32_t)(2*sp + 1) * 32;
                uint32_t A0[4], A1[4], B0[8], B1[8];
                ldsm4(A0, abase + o0);
                ldsm4(A1, abase + o1);
                ldsm4(B0 + 0, bbase0 + o0);  ldsm4(B0 + 4, bbase1 + o0);
                ldsm4(B1 + 0, bbase0 + o1);  ldsm4(B1 + 4, bbase1 + o1);
                #pragma unroll
                for (int nt = 0; nt < 4; nt++) {
                    if (STAGE == 1) {
                        // exact integer arithmetic: chain everything
                        mma_acc(acc[nt], A0, B0[nt*2], B0[nt*2+1]);
                        mma_acc(acc[nt], A1, B1[nt*2], B1[nt*2+1]);
                    } else {
                        // pair-chain in TC, RN-fold per pair (FFMA-class error)
                        float d[4] = {0.f, 0.f, 0.f, 0.f};
                        mma_acc(d, A0, B0[nt*2], B0[nt*2+1]);
                        mma_acc(d, A1, B1[nt*2], B1[nt*2+1]);
                        acc[nt][0] += d[0]; acc[nt][1] += d[1];
                        acc[nt][2] += d[2]; acc[nt][3] += d[3];
                    }
                }
            }
            __syncthreads();   // all warps done reading A before next build
        }

        // ---- epilogue (verbatim R11) ----
        const int p0 = wid*16 + g;     // D rows for c0/c1
        const int p1 = p0 + 8;         // D rows for c2/c3
        if (STAGE == 0) {
            size_t base0 = (size_t)b*CL_PLANE + (((size_t)y*WW + x0 + p0) << 5);
            size_t base1 = (size_t)b*CL_PLANE + (((size_t)y*WW + x0 + p1) << 5);
            #pragma unroll
            for (int nt = 0; nt < 4; nt++) {
                int l00 = lut_level(acc[nt][0], t0r[nt*2+0], dfr[nt*2+0]);
                int l01 = lut_level(acc[nt][1], t0r[nt*2+1], dfr[nt*2+1]);
                int l10 = lut_level(acc[nt][2], t0r[nt*2+0], dfr[nt*2+0]);
                int l11 = lut_level(acc[nt][3], t0r[nt*2+1], dfr[nt*2+1]);
                *(uint32_t*)(g_lev + base0 + nt*8 + 2*tg) =
                    bf16bits_of_int(l00) | (bf16bits_of_int(l01) << 16);
                *(uint32_t*)(g_lev + base1 + nt*8 + 2*tg) =
                    bf16bits_of_int(l10) | (bf16bits_of_int(l11) << 16);
            }
        } else {
            // bounce through smem as [co][DF_PITCH] for coalesced NCHW stores
            #pragma unroll
            for (int nt = 0; nt < 4; nt++) {
                int c0 = nt*8 + 2*tg, c1 = c0 + 1;
                Df[c0*DF_PITCH + p0] = (float)lut_level(acc[nt][0], t0r[nt*2+0], dfr[nt*2+0]);
                Df[c1*DF_PITCH + p0] = (float)lut_level(acc[nt][1], t0r[nt*2+1], dfr[nt*2+1]);
                Df[c0*DF_PITCH + p1] = (float)lut_level(acc[nt][2], t0r[nt*2+0], dfr[nt*2+0]);
                Df[c1*DF_PITCH + p1] = (float)lut_level(acc[nt][3], t0r[nt*2+1], dfr[nt*2+1]);
            }
            __syncthreads();
            {
                int co = tid >> 3, ch = tid & 7;
                int px = ch * 16;
                const uint4* s4 = (const uint4*)(Df + co*DF_PITCH + px);
                uint4* o4 = (uint4*)(outp + (size_t)b*CC*NPIX + (size_t)co*NPIX
                                          + (size_t)y*WW + x0 + px);
                o4[0] = s4[0]; o4[1] = s4[1]; o4[2] = s4[2]; o4[3] = s4[3];
            }
            __syncthreads();   // Df region becomes A again next tile
        }
    }
}

// ---------------------------------------------------------------------------
extern "C" void kernel_launch(void* const* d_in, const int* in_sizes, int n_in,
                              void* d_out, int out_size)
{
    const float* x    = (const float*)d_in[0];
    const float* w1   = (const float*)d_in[1];
    const float* w2   = (const float*)d_in[2];
    const float* bn1w = (const float*)d_in[3];
    const float* bn1b = (const float*)d_in[4];
    const float* bn1m = (const float*)d_in[5];
    const float* bn1v = (const float*)d_in[6];
    const float* bn2w = (const float*)d_in[7];
    const float* bn2b = (const float*)d_in[8];
    const float* bn2m = (const float*)d_in[9];
    const float* bn2v = (const float*)d_in[10];
    const float* a1   = (const float*)d_in[11];
    const float* a2   = (const float*)d_in[12];
    const float* ns   = (const float*)d_in[13];

    prep_kernel<<<1, 256>>>(w1, w2, bn1w, bn1b, bn1m, bn1v,
                            bn2w, bn2b, bn2m, bn2v, a1, a2, ns);
    split_kernel<<<BB*HH, 256>>>(x);

    cudaFuncSetAttribute(conv_mma_kernel<0>, cudaFuncAttributeMaxDynamicSharedMemorySize, SMEM_BYTES);
    cudaFuncSetAttribute(conv_mma_kernel<1>, cudaFuncAttributeMaxDynamicSharedMemorySize, SMEM_BYTES);

    conv_mma_kernel<0><<<296, 256, SMEM_BYTES>>>(nullptr);
    conv_mma_kernel<1><<<296, 256, SMEM_BYTES>>>((float*)d_out);
}